// round 9
// baseline (speedup 1.0000x reference)
#include <cuda_runtime.h>
#include <cuda_bf16.h>
#include <cuda_fp16.h>
#include <cstdint>

#define NODES 100000
#define EDGES 3200000
#define BN_EPS 1e-5f

// ---------------- scratch (no allocation allowed) ----------------
__device__ float g_z[NODES * 256];   // z = h + agg
__device__ float g_m[NODES * 256];   // after first linear+BN+ReLU
__device__ float g_h[NODES * 256];   // layer output (fp32)
__device__ __align__(16) __half g_h16[NODES * 256];  // fp16 mirror for gather
__device__ int   g_counts[NODES];
__device__ int   g_offsets[NODES];
__device__ int   g_cursor[NODES];
__device__ int   g_blocksums[128];
__device__ int   g_csr[EDGES];
// weight images per GEMM: Bt_hi[256][K] bf16, then Bt_lo[256][K] bf16 (k-major)
__device__ __align__(16) unsigned char g_wimg[6][262144];

// ---------------- helpers ----------------
__device__ __forceinline__ uint32_t smem_u32(const void* p) {
    uint32_t a;
    asm("{ .reg .u64 t; cvta.to.shared.u64 t, %1; cvt.u32.u64 %0, t; }" : "=r"(a) : "l"(p));
    return a;
}
__device__ __forceinline__ void ldsm4(uint32_t* r, uint32_t addr) {
    asm volatile("ldmatrix.sync.aligned.m8n8.x4.shared.b16 {%0,%1,%2,%3}, [%4];"
        : "=r"(r[0]), "=r"(r[1]), "=r"(r[2]), "=r"(r[3]) : "r"(addr));
}
__device__ __forceinline__ void ldsm2(uint32_t* r, uint32_t addr) {
    asm volatile("ldmatrix.sync.aligned.m8n8.x2.shared.b16 {%0,%1}, [%2];"
        : "=r"(r[0]), "=r"(r[1]) : "r"(addr));
}
__device__ __forceinline__ void mma16816(float* d, const uint32_t* a, const uint32_t* b) {
    asm volatile(
        "mma.sync.aligned.m16n8k16.row.col.f32.bf16.bf16.f32 "
        "{%0,%1,%2,%3}, {%4,%5,%6,%7}, {%8,%9}, {%0,%1,%2,%3};"
        : "+f"(d[0]), "+f"(d[1]), "+f"(d[2]), "+f"(d[3])
        : "r"(a[0]), "r"(a[1]), "r"(a[2]), "r"(a[3]), "r"(b[0]), "r"(b[1]));
}
__device__ __forceinline__ void bfsplit(float v, unsigned short& hi, unsigned short& lo) {
    __nv_bfloat16 hb = __float2bfloat16(v);
    __nv_bfloat16 lb = __float2bfloat16(v - __bfloat162float(hb));
    hi = reinterpret_cast<unsigned short&>(hb);
    lo = reinterpret_cast<unsigned short&>(lb);
}

// ---------------- CSR build ----------------
__global__ void zero_counts_kernel() {
    int i = blockIdx.x * blockDim.x + threadIdx.x;
    if (i < NODES) g_counts[i] = 0;
}
__global__ void hist_kernel(const int* __restrict__ dst) {
    int e = blockIdx.x * blockDim.x + threadIdx.x;
    if (e < EDGES) atomicAdd(&g_counts[dst[e]], 1);
}
#define SCAN_CHUNK 1024
#define SCAN_NB ((NODES + SCAN_CHUNK - 1) / SCAN_CHUNK)   // 98
__global__ void scan1_kernel() {
    __shared__ int s[SCAN_CHUNK];
    int t = threadIdx.x;
    int i = blockIdx.x * SCAN_CHUNK + t;
    s[t] = (i < NODES) ? g_counts[i] : 0;
    __syncthreads();
    for (int d = SCAN_CHUNK / 2; d > 0; d >>= 1) {
        if (t < d) s[t] += s[t + d];
        __syncthreads();
    }
    if (t == 0) g_blocksums[blockIdx.x] = s[0];
}
__global__ void scan2_kernel() {
    __shared__ int s[128];
    int t = threadIdx.x;
    int v = (t < SCAN_NB) ? g_blocksums[t] : 0;
    s[t] = v;
    __syncthreads();
    for (int d = 1; d < 128; d <<= 1) {
        int x = (t >= d) ? s[t - d] : 0;
        __syncthreads();
        s[t] += x;
        __syncthreads();
    }
    g_blocksums[t] = s[t] - v;   // exclusive
}
__global__ void scan3_kernel() {
    __shared__ int s[SCAN_CHUNK];
    int t = threadIdx.x;
    int i = blockIdx.x * SCAN_CHUNK + t;
    int v = (i < NODES) ? g_counts[i] : 0;
    s[t] = v;
    __syncthreads();
    for (int d = 1; d < SCAN_CHUNK; d <<= 1) {
        int x = (t >= d) ? s[t - d] : 0;
        __syncthreads();
        s[t] += x;
        __syncthreads();
    }
    int off = g_blocksums[blockIdx.x] + s[t] - v;
    if (i < NODES) {
        g_offsets[i] = off;
        g_cursor[i]  = off;
    }
}
__global__ void scatter_kernel(const int* __restrict__ src, const int* __restrict__ dst) {
    int e = blockIdx.x * blockDim.x + threadIdx.x;
    if (e < EDGES) {
        int d = dst[e];
        int pos = atomicAdd(&g_cursor[d], 1);
        g_csr[pos] = src[e];
    }
}

// ---------------- x -> fp16 convert (for layer-1 gather) ----------------
__global__ void xhalf_kernel(const float* __restrict__ x, __half* __restrict__ x16) {
    int t = blockIdx.x * blockDim.x + threadIdx.x;   // one per 4 floats
    if (t < NODES * 32) {
        float4 v = ((const float4*)x)[t];
        __half2 a = __floats2half2_rn(v.x, v.y);
        __half2 b = __floats2half2_rn(v.z, v.w);
        ((__half2*)x16)[t * 2]     = a;
        ((__half2*)x16)[t * 2 + 1] = b;
    }
}

// ---------------- aggregation: self fp32 + fp16 neighbor gather (4-edge MLP) ----------------
template <int F>
__global__ void agg_kernel(const float* __restrict__ hf, const __half* __restrict__ h16,
                           float* __restrict__ z) {
    constexpr int TPN = F / 8;                // lanes per node (8 features each)
    constexpr int NPB = 256 / TPN;
    int node = blockIdx.x * NPB + threadIdx.y;
    if (node >= NODES) return;
    int f = threadIdx.x;
    const float4* selfp = (const float4*)(hf + (size_t)node * F) + f * 2;
    float4 a0 = selfp[0], a1 = selfp[1];
    float acc0 = a0.x, acc1 = a0.y, acc2 = a0.z, acc3 = a0.w;
    float acc4 = a1.x, acc5 = a1.y, acc6 = a1.z, acc7 = a1.w;
    const uint4* __restrict__ g16 = (const uint4*)h16;
    int beg = g_offsets[node];
    int cnt = g_counts[node];
    int k = 0;
#define ACCQ(Q) do { \
        float2 p0 = __half22float2(*(__half2*)&(Q).x); \
        float2 p1 = __half22float2(*(__half2*)&(Q).y); \
        float2 p2 = __half22float2(*(__half2*)&(Q).z); \
        float2 p3 = __half22float2(*(__half2*)&(Q).w); \
        acc0 += p0.x; acc1 += p0.y; acc2 += p1.x; acc3 += p1.y; \
        acc4 += p2.x; acc5 += p2.y; acc6 += p3.x; acc7 += p3.y; } while (0)
    for (; k + 4 <= cnt; k += 4) {
        int j0 = g_csr[beg + k];
        int j1 = g_csr[beg + k + 1];
        int j2 = g_csr[beg + k + 2];
        int j3 = g_csr[beg + k + 3];
        uint4 q0 = __ldg(&g16[(size_t)j0 * TPN + f]);
        uint4 q1 = __ldg(&g16[(size_t)j1 * TPN + f]);
        uint4 q2 = __ldg(&g16[(size_t)j2 * TPN + f]);
        uint4 q3 = __ldg(&g16[(size_t)j3 * TPN + f]);
        ACCQ(q0); ACCQ(q1); ACCQ(q2); ACCQ(q3);
    }
    for (; k < cnt; k++) {
        int j = g_csr[beg + k];
        uint4 q = __ldg(&g16[(size_t)j * TPN + f]);
        ACCQ(q);
    }
#undef ACCQ
    float4* zp = (float4*)(z + (size_t)node * F) + f * 2;
    zp[0] = make_float4(acc0, acc1, acc2, acc3);
    zp[1] = make_float4(acc4, acc5, acc6, acc7);
}

// ---------------- weight prep: W[K,256] fp32 -> Bt_hi[256][K], Bt_lo[256][K] bf16 ----------------
__global__ void prep_kernel(const float* __restrict__ W, int K, unsigned char* __restrict__ img) {
    int t = blockIdx.x * blockDim.x + threadIdx.x;
    if (t >= 256 * K) return;
    int n = t / K;
    int k = t % K;
    float v = W[(size_t)k * 256 + n];
    unsigned short hi, lo;
    bfsplit(v, hi, lo);
    ((unsigned short*)img)[t] = hi;
    ((unsigned short*)(img + 256 * K * 2))[t] = lo;
}

// ---------------- tensor-core GEMM: C[M,256] = A[M,K] @ W[K,256], bf16x3 split ----------------
// CTA 128x128, 8 warps (4 M x 2 N), warp tile 32x64, K chunk 32.  (round-3 proven config)
#define AROW 80
__global__ void __launch_bounds__(256, 2) gemm_mma(
    const float* __restrict__ A, const unsigned char* __restrict__ img,
    float* __restrict__ C, __half* __restrict__ C16, int K,
    const float* __restrict__ bias, const float* __restrict__ gamma,
    const float* __restrict__ beta, const float* __restrict__ mu,
    const float* __restrict__ var, int mode)
{
    __shared__ float s_sc[128];
    __shared__ float s_sh[128];
    __shared__ __align__(16) unsigned char s_ah[128 * AROW];
    __shared__ __align__(16) unsigned char s_al[128 * AROW];
    __shared__ __align__(16) unsigned char s_bh[128 * AROW];
    __shared__ __align__(16) unsigned char s_bl[128 * AROW];

    int tid = threadIdx.x;
    int wid = tid >> 5, lane = tid & 31;
    int wm = wid & 3, wn = wid >> 2;          // 4 M-warps x 2 N-warps
    int m0 = blockIdx.x * 128;
    int bn = blockIdx.y;                      // N half (0/1)

    if (tid < 128) {
        int col = bn * 128 + tid;
        float s, h;
        if (mode == 0) {
            s = gamma[col] * rsqrtf(var[col] + BN_EPS);
            h = beta[col] + (bias[col] - mu[col]) * s;
        } else {
            s = 1.f;
            h = bias[col];
        }
        s_sc[tid] = s;
        s_sh[tid] = h;
    }

    float acc[2][8][4];
#pragma unroll
    for (int i = 0; i < 2; i++)
#pragma unroll
        for (int j = 0; j < 8; j++)
#pragma unroll
            for (int q = 0; q < 4; q++) acc[i][j][q] = 0.f;

    uint32_t ah_b = smem_u32(s_ah), al_b = smem_u32(s_al);
    uint32_t bh_b = smem_u32(s_bh), bl_b = smem_u32(s_bl);
    int l16 = lane & 15;
    uint32_t a_off = (uint32_t)((wm * 32 + l16) * AROW + (lane >> 4) * 16);
    uint32_t b_off = (uint32_t)((wn * 64 + (l16 & 7)) * AROW + ((l16 >> 3) & 1) * 16);

    int nchunk = K >> 5;
    for (int c = 0; c < nchunk; c++) {
        if (c) __syncthreads();
        // ---- A chunk: 128 rows x 32 k fp32 -> bf16 hi/lo ----
#pragma unroll
        for (int i = 0; i < 4; i++) {
            int idx = tid + i * 256;
            int row = idx >> 3, q = idx & 7;
            float4 v = make_float4(0.f, 0.f, 0.f, 0.f);
            if (m0 + row < NODES)
                v = *(const float4*)&A[(size_t)(m0 + row) * K + c * 32 + q * 4];
            unsigned short h0, h1, h2, h3, l0, l1, l2, l3;
            bfsplit(v.x, h0, l0); bfsplit(v.y, h1, l1);
            bfsplit(v.z, h2, l2); bfsplit(v.w, h3, l3);
            uint2 hp = make_uint2(((uint32_t)h1 << 16) | h0, ((uint32_t)h3 << 16) | h2);
            uint2 lp = make_uint2(((uint32_t)l1 << 16) | l0, ((uint32_t)l3 << 16) | l2);
            *(uint2*)(s_ah + row * AROW + q * 8) = hp;
            *(uint2*)(s_al + row * AROW + q * 8) = lp;
        }
        // ---- B chunk: 128 n-rows x 32 k bf16 hi/lo (pre-split, k-major) ----
#pragma unroll
        for (int i = 0; i < 2; i++) {
            int idx = tid + i * 256;
            int row = idx >> 2, q = idx & 3;
            size_t srcoff = ((size_t)(bn * 128 + row) * K + c * 32) * 2 + q * 16;
            *(uint4*)(s_bh + row * AROW + q * 16) = *(const uint4*)(img + srcoff);
            *(uint4*)(s_bl + row * AROW + q * 16) = *(const uint4*)(img + 256 * (size_t)K * 2 + srcoff);
        }
        __syncthreads();

#pragma unroll
        for (int ks = 0; ks < 2; ks++) {
            uint32_t a_hi[2][4], a_lo[2][4];
#pragma unroll
            for (int mt = 0; mt < 2; mt++) {
                ldsm4(a_hi[mt], ah_b + a_off + mt * 16 * AROW + ks * 32);
                ldsm4(a_lo[mt], al_b + a_off + mt * 16 * AROW + ks * 32);
            }
#pragma unroll
            for (int nh = 0; nh < 2; nh++) {
                uint32_t b_hi[4][2], b_lo[4][2];
#pragma unroll
                for (int t4 = 0; t4 < 4; t4++) {
                    int nt = nh * 4 + t4;
                    ldsm2(b_hi[t4], bh_b + b_off + nt * 8 * AROW + ks * 32);
                    ldsm2(b_lo[t4], bl_b + b_off + nt * 8 * AROW + ks * 32);
                }
#pragma unroll
                for (int mt = 0; mt < 2; mt++)
#pragma unroll
                    for (int t4 = 0; t4 < 4; t4++) {
                        int nt = nh * 4 + t4;
                        mma16816(acc[mt][nt], a_hi[mt], b_hi[t4]);
                        mma16816(acc[mt][nt], a_lo[mt], b_hi[t4]);
                        mma16816(acc[mt][nt], a_hi[mt], b_lo[t4]);
                    }
            }
        }
    }

    // ---- epilogue ----
#pragma unroll
    for (int mt = 0; mt < 2; mt++) {
        int row0 = m0 + wm * 32 + mt * 16 + (lane >> 2);
#pragma unroll
        for (int nt = 0; nt < 8; nt++) {
            int colL = wn * 64 + nt * 8 + (lane & 3) * 2;
            float sc0 = s_sc[colL], sc1 = s_sc[colL + 1];
            float sh0 = s_sh[colL], sh1 = s_sh[colL + 1];
            float v0 = acc[mt][nt][0] * sc0 + sh0;
            float v1 = acc[mt][nt][1] * sc1 + sh1;
            float v2 = acc[mt][nt][2] * sc0 + sh0;
            float v3 = acc[mt][nt][3] * sc1 + sh1;
            if (mode < 2) {
                v0 = fmaxf(v0, 0.f); v1 = fmaxf(v1, 0.f);
                v2 = fmaxf(v2, 0.f); v3 = fmaxf(v3, 0.f);
            }
            int colG = bn * 128 + colL;
            if (row0 < NODES) {
                *(float2*)&C[(size_t)row0 * 256 + colG] = make_float2(v0, v1);
                if (mode == 1)
                    *(__half2*)&C16[(size_t)row0 * 256 + colG] = __floats2half2_rn(v0, v1);
            }
            if (row0 + 8 < NODES) {
                *(float2*)&C[(size_t)(row0 + 8) * 256 + colG] = make_float2(v2, v3);
                if (mode == 1)
                    *(__half2*)&C16[(size_t)(row0 + 8) * 256 + colG] = __floats2half2_rn(v2, v3);
            }
        }
    }
}

// ---------------- output head ----------------
__global__ void out_kernel(const float* __restrict__ h, const float* __restrict__ W,
                           const float* __restrict__ b, float* __restrict__ out) {
    int gw = (blockIdx.x * blockDim.x + threadIdx.x) >> 5;
    int lane = threadIdx.x & 31;
    if (gw >= NODES) return;
    const float* row = h + (size_t)gw * 256;
    float a0 = 0.f, a1 = 0.f;
    for (int k = lane; k < 256; k += 32) {
        float v = row[k];
        a0 += v * W[k * 2];
        a1 += v * W[k * 2 + 1];
    }
#pragma unroll
    for (int o = 16; o > 0; o >>= 1) {
        a0 += __shfl_down_sync(0xFFFFFFFFu, a0, o);
        a1 += __shfl_down_sync(0xFFFFFFFFu, a1, o);
    }
    if (lane == 0) {
        out[gw * 2]     = a0 + b[0];
        out[gw * 2 + 1] = a1 + b[1];
    }
}

// ---------------- launch ----------------
extern "C" void kernel_launch(void* const* d_in, const int* in_sizes, int n_in,
                              void* d_out, int out_size) {
    const float* x   = (const float*)d_in[0];
    const int*   ei  = (const int*)d_in[1];
    const int*   src = ei;
    const int*   dst = ei + EDGES;

    const float* L[3][8];
    for (int l = 0; l < 3; l++)
        for (int p = 0; p < 8; p++)
            L[l][p] = (const float*)d_in[2 + l * 8 + p];
    const float* out_W = (const float*)d_in[26];
    const float* out_b = (const float*)d_in[27];
    float* out = (float*)d_out;

    float* zp; cudaGetSymbolAddress((void**)&zp, g_z);
    float* mp; cudaGetSymbolAddress((void**)&mp, g_m);
    float* hp; cudaGetSymbolAddress((void**)&hp, g_h);
    __half* h16; cudaGetSymbolAddress((void**)&h16, g_h16);
    unsigned char* wimg; cudaGetSymbolAddress((void**)&wimg, g_wimg);

    // CSR build
    zero_counts_kernel<<<(NODES + 255) / 256, 256>>>();
    hist_kernel<<<(EDGES + 255) / 256, 256>>>(dst);
    scan1_kernel<<<SCAN_NB, SCAN_CHUNK>>>();
    scan2_kernel<<<1, 128>>>();
    scan3_kernel<<<SCAN_NB, SCAN_CHUNK>>>();
    scatter_kernel<<<(EDGES + 255) / 256, 256>>>(src, dst);

    // weight images + x fp16 mirror
    const float* Ws[6] = { L[0][0], L[0][6], L[1][0], L[1][6], L[2][0], L[2][6] };
    int Ks[6] = { 128, 256, 256, 256, 256, 256 };
    for (int i = 0; i < 6; i++) {
        int total = 256 * Ks[i];
        prep_kernel<<<(total + 255) / 256, 256>>>(Ws[i], Ks[i], wimg + (size_t)i * 262144);
    }
    xhalf_kernel<<<(NODES * 32 + 255) / 256, 256>>>(x, h16);

    dim3 ggrid((NODES + 127) / 128, 2);   // 782 x 2

    // layer 1  (gather x in fp16; h16 holds x16 with stride 128)
    agg_kernel<128><<<(NODES + 15) / 16, dim3(16, 16)>>>(x, h16, zp);
    gemm_mma<<<ggrid, 256>>>(zp, wimg + 0 * 262144, mp, nullptr, 128,
                             L[0][1], L[0][2], L[0][3], L[0][4], L[0][5], 0);
    gemm_mma<<<ggrid, 256>>>(mp, wimg + 1 * 262144, hp, h16, 256,
                             L[0][7], nullptr, nullptr, nullptr, nullptr, 1);
    // layer 2
    agg_kernel<256><<<(NODES + 7) / 8, dim3(32, 8)>>>(hp, h16, zp);
    gemm_mma<<<ggrid, 256>>>(zp, wimg + 2 * 262144, mp, nullptr, 256,
                             L[1][1], L[1][2], L[1][3], L[1][4], L[1][5], 0);
    gemm_mma<<<ggrid, 256>>>(mp, wimg + 3 * 262144, hp, h16, 256,
                             L[1][7], nullptr, nullptr, nullptr, nullptr, 1);
    // layer 3
    agg_kernel<256><<<(NODES + 7) / 8, dim3(32, 8)>>>(hp, h16, zp);
    gemm_mma<<<ggrid, 256>>>(zp, wimg + 4 * 262144, mp, nullptr, 256,
                             L[2][1], L[2][2], L[2][3], L[2][4], L[2][5], 0);
    gemm_mma<<<ggrid, 256>>>(mp, wimg + 5 * 262144, hp, nullptr, 256,
                             L[2][7], nullptr, nullptr, nullptr, nullptr, 2);

    // output head
    out_kernel<<<(NODES * 32 + 255) / 256, 256>>>(hp, out_W, out_b, out);
}

// round 10
// speedup vs baseline: 1.4771x; 1.4771x over previous
#include <cuda_runtime.h>
#include <cuda_bf16.h>
#include <cuda_fp16.h>
#include <cstdint>

#define NODES 100000
#define EDGES 3200000
#define BN_EPS 1e-5f

// ---------------- scratch (no allocation allowed) ----------------
__device__ float g_z[NODES * 256];   // z = h + agg
__device__ float g_m[NODES * 256];   // after first linear+BN+ReLU
__device__ float g_h[NODES * 256];   // layer output (fp32)
__device__ __align__(16) __half g_h16[NODES * 256];  // fp16 mirror for gather
__device__ int   g_counts[NODES];
__device__ int   g_offsets[NODES];
__device__ int   g_cursor[NODES];
__device__ int   g_blocksums[128];
__device__ int   g_csr[EDGES];
// weight images per GEMM: Bt_hi[256][K] bf16, then Bt_lo[256][K] bf16 (k-major)
__device__ __align__(16) unsigned char g_wimg[6][262144];

// ---------------- helpers ----------------
__device__ __forceinline__ uint32_t smem_u32(const void* p) {
    uint32_t a;
    asm("{ .reg .u64 t; cvta.to.shared.u64 t, %1; cvt.u32.u64 %0, t; }" : "=r"(a) : "l"(p));
    return a;
}
__device__ __forceinline__ void ldsm4(uint32_t* r, uint32_t addr) {
    asm volatile("ldmatrix.sync.aligned.m8n8.x4.shared.b16 {%0,%1,%2,%3}, [%4];"
        : "=r"(r[0]), "=r"(r[1]), "=r"(r[2]), "=r"(r[3]) : "r"(addr));
}
__device__ __forceinline__ void ldsm2(uint32_t* r, uint32_t addr) {
    asm volatile("ldmatrix.sync.aligned.m8n8.x2.shared.b16 {%0,%1}, [%2];"
        : "=r"(r[0]), "=r"(r[1]) : "r"(addr));
}
__device__ __forceinline__ void mma16816(float* d, const uint32_t* a, const uint32_t* b) {
    asm volatile(
        "mma.sync.aligned.m16n8k16.row.col.f32.bf16.bf16.f32 "
        "{%0,%1,%2,%3}, {%4,%5,%6,%7}, {%8,%9}, {%0,%1,%2,%3};"
        : "+f"(d[0]), "+f"(d[1]), "+f"(d[2]), "+f"(d[3])
        : "r"(a[0]), "r"(a[1]), "r"(a[2]), "r"(a[3]), "r"(b[0]), "r"(b[1]));
}
__device__ __forceinline__ void bfsplit(float v, unsigned short& hi, unsigned short& lo) {
    __nv_bfloat16 hb = __float2bfloat16(v);
    __nv_bfloat16 lb = __float2bfloat16(v - __bfloat162float(hb));
    hi = reinterpret_cast<unsigned short&>(hb);
    lo = reinterpret_cast<unsigned short&>(lb);
}

// ---------------- CSR build ----------------
__global__ void zero_counts_kernel() {
    int i = blockIdx.x * blockDim.x + threadIdx.x;
    if (i < NODES) g_counts[i] = 0;
}
__global__ void hist_kernel(const int* __restrict__ dst) {
    int e = blockIdx.x * blockDim.x + threadIdx.x;
    if (e < EDGES) atomicAdd(&g_counts[dst[e]], 1);
}
#define SCAN_CHUNK 1024
#define SCAN_NB ((NODES + SCAN_CHUNK - 1) / SCAN_CHUNK)   // 98
__global__ void scan1_kernel() {
    __shared__ int s[SCAN_CHUNK];
    int t = threadIdx.x;
    int i = blockIdx.x * SCAN_CHUNK + t;
    s[t] = (i < NODES) ? g_counts[i] : 0;
    __syncthreads();
    for (int d = SCAN_CHUNK / 2; d > 0; d >>= 1) {
        if (t < d) s[t] += s[t + d];
        __syncthreads();
    }
    if (t == 0) g_blocksums[blockIdx.x] = s[0];
}
__global__ void scan2_kernel() {
    __shared__ int s[128];
    int t = threadIdx.x;
    int v = (t < SCAN_NB) ? g_blocksums[t] : 0;
    s[t] = v;
    __syncthreads();
    for (int d = 1; d < 128; d <<= 1) {
        int x = (t >= d) ? s[t - d] : 0;
        __syncthreads();
        s[t] += x;
        __syncthreads();
    }
    g_blocksums[t] = s[t] - v;   // exclusive
}
__global__ void scan3_kernel() {
    __shared__ int s[SCAN_CHUNK];
    int t = threadIdx.x;
    int i = blockIdx.x * SCAN_CHUNK + t;
    int v = (i < NODES) ? g_counts[i] : 0;
    s[t] = v;
    __syncthreads();
    for (int d = 1; d < SCAN_CHUNK; d <<= 1) {
        int x = (t >= d) ? s[t - d] : 0;
        __syncthreads();
        s[t] += x;
        __syncthreads();
    }
    int off = g_blocksums[blockIdx.x] + s[t] - v;
    if (i < NODES) {
        g_offsets[i] = off;
        g_cursor[i]  = off;
    }
}
__global__ void scatter_kernel(const int* __restrict__ src, const int* __restrict__ dst) {
    int e = blockIdx.x * blockDim.x + threadIdx.x;
    if (e < EDGES) {
        int d = dst[e];
        int pos = atomicAdd(&g_cursor[d], 1);
        g_csr[pos] = src[e];
    }
}

// ---------------- x -> fp16 convert (for layer-1 gather) ----------------
__global__ void xhalf_kernel(const float* __restrict__ x, __half* __restrict__ x16) {
    int t = blockIdx.x * blockDim.x + threadIdx.x;   // one per 4 floats
    if (t < NODES * 32) {
        float4 v = ((const float4*)x)[t];
        __half2 a = __floats2half2_rn(v.x, v.y);
        __half2 b = __floats2half2_rn(v.z, v.w);
        ((__half2*)x16)[t * 2]     = a;
        ((__half2*)x16)[t * 2 + 1] = b;
    }
}

// ---------------- aggregation: self fp32 + fp16 neighbor gather (depth-1 prefetch) ----------------
template <int F>
__global__ void agg_kernel(const float* __restrict__ hf, const __half* __restrict__ h16,
                           float* __restrict__ z) {
    constexpr int TPN = F / 8;                // lanes per node (8 features each)
    constexpr int NPB = 256 / TPN;
    int node = blockIdx.x * NPB + threadIdx.y;
    if (node >= NODES) return;
    int f = threadIdx.x;
    const float4* selfp = (const float4*)(hf + (size_t)node * F) + f * 2;
    float4 a0 = selfp[0], a1 = selfp[1];
    float acc0 = a0.x, acc1 = a0.y, acc2 = a0.z, acc3 = a0.w;
    float acc4 = a1.x, acc5 = a1.y, acc6 = a1.z, acc7 = a1.w;
    const uint4* __restrict__ g16 = (const uint4*)h16;
    int beg = g_offsets[node];
    int cnt = g_counts[node];
#define ACCQ(Q) do { \
        float2 p0 = __half22float2(*(__half2*)&(Q).x); \
        float2 p1 = __half22float2(*(__half2*)&(Q).y); \
        float2 p2 = __half22float2(*(__half2*)&(Q).z); \
        float2 p3 = __half22float2(*(__half2*)&(Q).w); \
        acc0 += p0.x; acc1 += p0.y; acc2 += p1.x; acc3 += p1.y; \
        acc4 += p2.x; acc5 += p2.y; acc6 += p3.x; acc7 += p3.y; } while (0)
    if (cnt > 0) {
        int j = g_csr[beg];
        uint4 q = __ldg(&g16[(size_t)j * TPN + f]);
        for (int k = 1; k < cnt; k++) {
            int jn = g_csr[beg + k];
            uint4 qn = __ldg(&g16[(size_t)jn * TPN + f]);
            ACCQ(q);
            q = qn;
        }
        ACCQ(q);
    }
#undef ACCQ
    float4* zp = (float4*)(z + (size_t)node * F) + f * 2;
    zp[0] = make_float4(acc0, acc1, acc2, acc3);
    zp[1] = make_float4(acc4, acc5, acc6, acc7);
}

// ---------------- weight prep: W[K,256] fp32 -> Bt_hi[256][K], Bt_lo[256][K] bf16 ----------------
__global__ void prep_kernel(const float* __restrict__ W, int K, unsigned char* __restrict__ img) {
    int t = blockIdx.x * blockDim.x + threadIdx.x;
    if (t >= 256 * K) return;
    int n = t / K;
    int k = t % K;
    float v = W[(size_t)k * 256 + n];
    unsigned short hi, lo;
    bfsplit(v, hi, lo);
    ((unsigned short*)img)[t] = hi;
    ((unsigned short*)(img + 256 * K * 2))[t] = lo;
}

// ---------------- tensor-core GEMM: C[M,256] = A[M,K] @ W[K,256], bf16x3 split ----------------
// CTA 128x128, 8 warps (4 M x 2 N), warp tile 32x64, K chunk 32.  (round-3 proven config)
#define AROW 80
__global__ void __launch_bounds__(256, 2) gemm_mma(
    const float* __restrict__ A, const unsigned char* __restrict__ img,
    float* __restrict__ C, __half* __restrict__ C16, int K,
    const float* __restrict__ bias, const float* __restrict__ gamma,
    const float* __restrict__ beta, const float* __restrict__ mu,
    const float* __restrict__ var, int mode)
{
    __shared__ float s_sc[128];
    __shared__ float s_sh[128];
    __shared__ __align__(16) unsigned char s_ah[128 * AROW];
    __shared__ __align__(16) unsigned char s_al[128 * AROW];
    __shared__ __align__(16) unsigned char s_bh[128 * AROW];
    __shared__ __align__(16) unsigned char s_bl[128 * AROW];

    int tid = threadIdx.x;
    int wid = tid >> 5, lane = tid & 31;
    int wm = wid & 3, wn = wid >> 2;          // 4 M-warps x 2 N-warps
    int m0 = blockIdx.x * 128;
    int bn = blockIdx.y;                      // N half (0/1)

    if (tid < 128) {
        int col = bn * 128 + tid;
        float s, h;
        if (mode == 0) {
            s = gamma[col] * rsqrtf(var[col] + BN_EPS);
            h = beta[col] + (bias[col] - mu[col]) * s;
        } else {
            s = 1.f;
            h = bias[col];
        }
        s_sc[tid] = s;
        s_sh[tid] = h;
    }

    float acc[2][8][4];
#pragma unroll
    for (int i = 0; i < 2; i++)
#pragma unroll
        for (int j = 0; j < 8; j++)
#pragma unroll
            for (int q = 0; q < 4; q++) acc[i][j][q] = 0.f;

    uint32_t ah_b = smem_u32(s_ah), al_b = smem_u32(s_al);
    uint32_t bh_b = smem_u32(s_bh), bl_b = smem_u32(s_bl);
    int l16 = lane & 15;
    uint32_t a_off = (uint32_t)((wm * 32 + l16) * AROW + (lane >> 4) * 16);
    uint32_t b_off = (uint32_t)((wn * 64 + (l16 & 7)) * AROW + ((l16 >> 3) & 1) * 16);

    int nchunk = K >> 5;
    for (int c = 0; c < nchunk; c++) {
        if (c) __syncthreads();
        // ---- A chunk: 128 rows x 32 k fp32 -> bf16 hi/lo ----
#pragma unroll
        for (int i = 0; i < 4; i++) {
            int idx = tid + i * 256;
            int row = idx >> 3, q = idx & 7;
            float4 v = make_float4(0.f, 0.f, 0.f, 0.f);
            if (m0 + row < NODES)
                v = *(const float4*)&A[(size_t)(m0 + row) * K + c * 32 + q * 4];
            unsigned short h0, h1, h2, h3, l0, l1, l2, l3;
            bfsplit(v.x, h0, l0); bfsplit(v.y, h1, l1);
            bfsplit(v.z, h2, l2); bfsplit(v.w, h3, l3);
            uint2 hp = make_uint2(((uint32_t)h1 << 16) | h0, ((uint32_t)h3 << 16) | h2);
            uint2 lp = make_uint2(((uint32_t)l1 << 16) | l0, ((uint32_t)l3 << 16) | l2);
            *(uint2*)(s_ah + row * AROW + q * 8) = hp;
            *(uint2*)(s_al + row * AROW + q * 8) = lp;
        }
        // ---- B chunk: 128 n-rows x 32 k bf16 hi/lo (pre-split, k-major) ----
#pragma unroll
        for (int i = 0; i < 2; i++) {
            int idx = tid + i * 256;
            int row = idx >> 2, q = idx & 3;
            size_t srcoff = ((size_t)(bn * 128 + row) * K + c * 32) * 2 + q * 16;
            *(uint4*)(s_bh + row * AROW + q * 16) = *(const uint4*)(img + srcoff);
            *(uint4*)(s_bl + row * AROW + q * 16) = *(const uint4*)(img + 256 * (size_t)K * 2 + srcoff);
        }
        __syncthreads();

#pragma unroll
        for (int ks = 0; ks < 2; ks++) {
            uint32_t a_hi[2][4], a_lo[2][4];
#pragma unroll
            for (int mt = 0; mt < 2; mt++) {
                ldsm4(a_hi[mt], ah_b + a_off + mt * 16 * AROW + ks * 32);
                ldsm4(a_lo[mt], al_b + a_off + mt * 16 * AROW + ks * 32);
            }
#pragma unroll
            for (int nh = 0; nh < 2; nh++) {
                uint32_t b_hi[4][2], b_lo[4][2];
#pragma unroll
                for (int t4 = 0; t4 < 4; t4++) {
                    int nt = nh * 4 + t4;
                    ldsm2(b_hi[t4], bh_b + b_off + nt * 8 * AROW + ks * 32);
                    ldsm2(b_lo[t4], bl_b + b_off + nt * 8 * AROW + ks * 32);
                }
#pragma unroll
                for (int mt = 0; mt < 2; mt++)
#pragma unroll
                    for (int t4 = 0; t4 < 4; t4++) {
                        int nt = nh * 4 + t4;
                        mma16816(acc[mt][nt], a_hi[mt], b_hi[t4]);
                        mma16816(acc[mt][nt], a_lo[mt], b_hi[t4]);
                        mma16816(acc[mt][nt], a_hi[mt], b_lo[t4]);
                    }
            }
        }
    }

    // ---- epilogue ----
#pragma unroll
    for (int mt = 0; mt < 2; mt++) {
        int row0 = m0 + wm * 32 + mt * 16 + (lane >> 2);
#pragma unroll
        for (int nt = 0; nt < 8; nt++) {
            int colL = wn * 64 + nt * 8 + (lane & 3) * 2;
            float sc0 = s_sc[colL], sc1 = s_sc[colL + 1];
            float sh0 = s_sh[colL], sh1 = s_sh[colL + 1];
            float v0 = acc[mt][nt][0] * sc0 + sh0;
            float v1 = acc[mt][nt][1] * sc1 + sh1;
            float v2 = acc[mt][nt][2] * sc0 + sh0;
            float v3 = acc[mt][nt][3] * sc1 + sh1;
            if (mode < 2) {
                v0 = fmaxf(v0, 0.f); v1 = fmaxf(v1, 0.f);
                v2 = fmaxf(v2, 0.f); v3 = fmaxf(v3, 0.f);
            }
            int colG = bn * 128 + colL;
            if (row0 < NODES) {
                *(float2*)&C[(size_t)row0 * 256 + colG] = make_float2(v0, v1);
                if (mode == 1)
                    *(__half2*)&C16[(size_t)row0 * 256 + colG] = __floats2half2_rn(v0, v1);
            }
            if (row0 + 8 < NODES) {
                *(float2*)&C[(size_t)(row0 + 8) * 256 + colG] = make_float2(v2, v3);
                if (mode == 1)
                    *(__half2*)&C16[(size_t)(row0 + 8) * 256 + colG] = __floats2half2_rn(v2, v3);
            }
        }
    }
}

// ---------------- output head ----------------
__global__ void out_kernel(const float* __restrict__ h, const float* __restrict__ W,
                           const float* __restrict__ b, float* __restrict__ out) {
    int gw = (blockIdx.x * blockDim.x + threadIdx.x) >> 5;
    int lane = threadIdx.x & 31;
    if (gw >= NODES) return;
    const float* row = h + (size_t)gw * 256;
    float a0 = 0.f, a1 = 0.f;
    for (int k = lane; k < 256; k += 32) {
        float v = row[k];
        a0 += v * W[k * 2];
        a1 += v * W[k * 2 + 1];
    }
#pragma unroll
    for (int o = 16; o > 0; o >>= 1) {
        a0 += __shfl_down_sync(0xFFFFFFFFu, a0, o);
        a1 += __shfl_down_sync(0xFFFFFFFFu, a1, o);
    }
    if (lane == 0) {
        out[gw * 2]     = a0 + b[0];
        out[gw * 2 + 1] = a1 + b[1];
    }
}

// ---------------- launch ----------------
extern "C" void kernel_launch(void* const* d_in, const int* in_sizes, int n_in,
                              void* d_out, int out_size) {
    const float* x   = (const float*)d_in[0];
    const int*   ei  = (const int*)d_in[1];
    const int*   src = ei;
    const int*   dst = ei + EDGES;

    const float* L[3][8];
    for (int l = 0; l < 3; l++)
        for (int p = 0; p < 8; p++)
            L[l][p] = (const float*)d_in[2 + l * 8 + p];
    const float* out_W = (const float*)d_in[26];
    const float* out_b = (const float*)d_in[27];
    float* out = (float*)d_out;

    float* zp; cudaGetSymbolAddress((void**)&zp, g_z);
    float* mp; cudaGetSymbolAddress((void**)&mp, g_m);
    float* hp; cudaGetSymbolAddress((void**)&hp, g_h);
    __half* h16; cudaGetSymbolAddress((void**)&h16, g_h16);
    unsigned char* wimg; cudaGetSymbolAddress((void**)&wimg, g_wimg);

    // CSR build
    zero_counts_kernel<<<(NODES + 255) / 256, 256>>>();
    hist_kernel<<<(EDGES + 255) / 256, 256>>>(dst);
    scan1_kernel<<<SCAN_NB, SCAN_CHUNK>>>();
    scan2_kernel<<<1, 128>>>();
    scan3_kernel<<<SCAN_NB, SCAN_CHUNK>>>();
    scatter_kernel<<<(EDGES + 255) / 256, 256>>>(src, dst);

    // weight images + x fp16 mirror
    const float* Ws[6] = { L[0][0], L[0][6], L[1][0], L[1][6], L[2][0], L[2][6] };
    int Ks[6] = { 128, 256, 256, 256, 256, 256 };
    for (int i = 0; i < 6; i++) {
        int total = 256 * Ks[i];
        prep_kernel<<<(total + 255) / 256, 256>>>(Ws[i], Ks[i], wimg + (size_t)i * 262144);
    }
    xhalf_kernel<<<(NODES * 32 + 255) / 256, 256>>>(x, h16);

    dim3 ggrid((NODES + 127) / 128, 2);   // 782 x 2

    // layer 1  (gather x in fp16; h16 holds x16 with stride 128)
    agg_kernel<128><<<(NODES + 15) / 16, dim3(16, 16)>>>(x, h16, zp);
    gemm_mma<<<ggrid, 256>>>(zp, wimg + 0 * 262144, mp, nullptr, 128,
                             L[0][1], L[0][2], L[0][3], L[0][4], L[0][5], 0);
    gemm_mma<<<ggrid, 256>>>(mp, wimg + 1 * 262144, hp, h16, 256,
                             L[0][7], nullptr, nullptr, nullptr, nullptr, 1);
    // layer 2
    agg_kernel<256><<<(NODES + 7) / 8, dim3(32, 8)>>>(hp, h16, zp);
    gemm_mma<<<ggrid, 256>>>(zp, wimg + 2 * 262144, mp, nullptr, 256,
                             L[1][1], L[1][2], L[1][3], L[1][4], L[1][5], 0);
    gemm_mma<<<ggrid, 256>>>(mp, wimg + 3 * 262144, hp, h16, 256,
                             L[1][7], nullptr, nullptr, nullptr, nullptr, 1);
    // layer 3
    agg_kernel<256><<<(NODES + 7) / 8, dim3(32, 8)>>>(hp, h16, zp);
    gemm_mma<<<ggrid, 256>>>(zp, wimg + 4 * 262144, mp, nullptr, 256,
                             L[2][1], L[2][2], L[2][3], L[2][4], L[2][5], 0);
    gemm_mma<<<ggrid, 256>>>(mp, wimg + 5 * 262144, hp, nullptr, 256,
                             L[2][7], nullptr, nullptr, nullptr, nullptr, 2);

    // output head
    out_kernel<<<(NODES * 32 + 255) / 256, 256>>>(hp, out_W, out_b, out);
}

// round 11
// speedup vs baseline: 1.7625x; 1.1933x over previous
#include <cuda_runtime.h>
#include <cuda_bf16.h>
#include <cuda_fp16.h>
#include <cstdint>

#define NODES 100000
#define EDGES 3200000
#define BN_EPS 1e-5f

// ---------------- scratch (no allocation allowed) ----------------
__device__ float g_z[NODES * 256];   // z = h + agg
__device__ float g_m[NODES * 256];   // after first linear+BN+ReLU
__device__ float g_h[NODES * 256];   // layer output (fp32)
__device__ __align__(16) __half g_h16[NODES * 256];  // fp16 mirror for gather
__device__ int   g_counts[NODES];
__device__ int   g_offsets[NODES];
__device__ int   g_cursor[NODES];
__device__ int   g_blocksums[128];
__device__ int   g_csr[EDGES];
// weight images per GEMM: Bt[256][K] fp16 (k-major), one plane
__device__ __align__(16) unsigned char g_wimg[6][131072];

// ---------------- helpers ----------------
__device__ __forceinline__ uint32_t smem_u32(const void* p) {
    uint32_t a;
    asm("{ .reg .u64 t; cvta.to.shared.u64 t, %1; cvt.u32.u64 %0, t; }" : "=r"(a) : "l"(p));
    return a;
}
__device__ __forceinline__ void ldsm4(uint32_t* r, uint32_t addr) {
    asm volatile("ldmatrix.sync.aligned.m8n8.x4.shared.b16 {%0,%1,%2,%3}, [%4];"
        : "=r"(r[0]), "=r"(r[1]), "=r"(r[2]), "=r"(r[3]) : "r"(addr));
}
__device__ __forceinline__ void ldsm2(uint32_t* r, uint32_t addr) {
    asm volatile("ldmatrix.sync.aligned.m8n8.x2.shared.b16 {%0,%1}, [%2];"
        : "=r"(r[0]), "=r"(r[1]) : "r"(addr));
}
__device__ __forceinline__ void mma16816h(float* d, const uint32_t* a, const uint32_t* b) {
    asm volatile(
        "mma.sync.aligned.m16n8k16.row.col.f32.f16.f16.f32 "
        "{%0,%1,%2,%3}, {%4,%5,%6,%7}, {%8,%9}, {%0,%1,%2,%3};"
        : "+f"(d[0]), "+f"(d[1]), "+f"(d[2]), "+f"(d[3])
        : "r"(a[0]), "r"(a[1]), "r"(a[2]), "r"(a[3]), "r"(b[0]), "r"(b[1]));
}
__device__ __forceinline__ void hsplit(float v, unsigned short& hi, unsigned short& lo) {
    __half hb = __float2half_rn(v);
    __half lb = __float2half_rn(v - __half2float(hb));
    hi = reinterpret_cast<unsigned short&>(hb);
    lo = reinterpret_cast<unsigned short&>(lb);
}

// ---------------- CSR build ----------------
__global__ void zero_counts_kernel() {
    int i = blockIdx.x * blockDim.x + threadIdx.x;
    if (i < NODES) g_counts[i] = 0;
}
__global__ void hist_kernel(const int* __restrict__ dst) {
    int e = blockIdx.x * blockDim.x + threadIdx.x;
    if (e < EDGES) atomicAdd(&g_counts[dst[e]], 1);
}
#define SCAN_CHUNK 1024
#define SCAN_NB ((NODES + SCAN_CHUNK - 1) / SCAN_CHUNK)   // 98
__global__ void scan1_kernel() {
    __shared__ int s[SCAN_CHUNK];
    int t = threadIdx.x;
    int i = blockIdx.x * SCAN_CHUNK + t;
    s[t] = (i < NODES) ? g_counts[i] : 0;
    __syncthreads();
    for (int d = SCAN_CHUNK / 2; d > 0; d >>= 1) {
        if (t < d) s[t] += s[t + d];
        __syncthreads();
    }
    if (t == 0) g_blocksums[blockIdx.x] = s[0];
}
__global__ void scan2_kernel() {
    __shared__ int s[128];
    int t = threadIdx.x;
    int v = (t < SCAN_NB) ? g_blocksums[t] : 0;
    s[t] = v;
    __syncthreads();
    for (int d = 1; d < 128; d <<= 1) {
        int x = (t >= d) ? s[t - d] : 0;
        __syncthreads();
        s[t] += x;
        __syncthreads();
    }
    g_blocksums[t] = s[t] - v;   // exclusive
}
__global__ void scan3_kernel() {
    __shared__ int s[SCAN_CHUNK];
    int t = threadIdx.x;
    int i = blockIdx.x * SCAN_CHUNK + t;
    int v = (i < NODES) ? g_counts[i] : 0;
    s[t] = v;
    __syncthreads();
    for (int d = 1; d < SCAN_CHUNK; d <<= 1) {
        int x = (t >= d) ? s[t - d] : 0;
        __syncthreads();
        s[t] += x;
        __syncthreads();
    }
    int off = g_blocksums[blockIdx.x] + s[t] - v;
    if (i < NODES) {
        g_offsets[i] = off;
        g_cursor[i]  = off;
    }
}
__global__ void scatter_kernel(const int* __restrict__ src, const int* __restrict__ dst) {
    int e = blockIdx.x * blockDim.x + threadIdx.x;
    if (e < EDGES) {
        int d = dst[e];
        int pos = atomicAdd(&g_cursor[d], 1);
        g_csr[pos] = src[e];
    }
}

// ---------------- x -> fp16 convert (for layer-1 gather) ----------------
__global__ void xhalf_kernel(const float* __restrict__ x, __half* __restrict__ x16) {
    int t = blockIdx.x * blockDim.x + threadIdx.x;   // one per 4 floats
    if (t < NODES * 32) {
        float4 v = ((const float4*)x)[t];
        __half2 a = __floats2half2_rn(v.x, v.y);
        __half2 b = __floats2half2_rn(v.z, v.w);
        ((__half2*)x16)[t * 2]     = a;
        ((__half2*)x16)[t * 2 + 1] = b;
    }
}

// ---------------- aggregation: self fp32 + fp16 neighbor gather (depth-1 prefetch) ----------------
template <int F>
__global__ void agg_kernel(const float* __restrict__ hf, const __half* __restrict__ h16,
                           float* __restrict__ z) {
    constexpr int TPN = F / 8;                // lanes per node (8 features each)
    constexpr int NPB = 256 / TPN;
    int node = blockIdx.x * NPB + threadIdx.y;
    if (node >= NODES) return;
    int f = threadIdx.x;
    const float4* selfp = (const float4*)(hf + (size_t)node * F) + f * 2;
    float4 a0 = selfp[0], a1 = selfp[1];
    float acc0 = a0.x, acc1 = a0.y, acc2 = a0.z, acc3 = a0.w;
    float acc4 = a1.x, acc5 = a1.y, acc6 = a1.z, acc7 = a1.w;
    const uint4* __restrict__ g16 = (const uint4*)h16;
    int beg = g_offsets[node];
    int cnt = g_counts[node];
#define ACCQ(Q) do { \
        float2 p0 = __half22float2(*(__half2*)&(Q).x); \
        float2 p1 = __half22float2(*(__half2*)&(Q).y); \
        float2 p2 = __half22float2(*(__half2*)&(Q).z); \
        float2 p3 = __half22float2(*(__half2*)&(Q).w); \
        acc0 += p0.x; acc1 += p0.y; acc2 += p1.x; acc3 += p1.y; \
        acc4 += p2.x; acc5 += p2.y; acc6 += p3.x; acc7 += p3.y; } while (0)
    if (cnt > 0) {
        int j = g_csr[beg];
        uint4 q = __ldg(&g16[(size_t)j * TPN + f]);
        for (int k = 1; k < cnt; k++) {
            int jn = g_csr[beg + k];
            uint4 qn = __ldg(&g16[(size_t)jn * TPN + f]);
            ACCQ(q);
            q = qn;
        }
        ACCQ(q);
    }
#undef ACCQ
    float4* zp = (float4*)(z + (size_t)node * F) + f * 2;
    zp[0] = make_float4(acc0, acc1, acc2, acc3);
    zp[1] = make_float4(acc4, acc5, acc6, acc7);
}

// ---------------- weight prep: W[K,256] fp32 -> Bt[256][K] fp16 (k-major) ----------------
__global__ void prep_kernel(const float* __restrict__ W, int K, unsigned char* __restrict__ img) {
    int t = blockIdx.x * blockDim.x + threadIdx.x;
    if (t >= 256 * K) return;
    int n = t / K;
    int k = t % K;
    float v = W[(size_t)k * 256 + n];
    __half hb = __float2half_rn(v);
    ((unsigned short*)img)[t] = reinterpret_cast<unsigned short&>(hb);
}

// ---------------- tensor-core GEMM: C[M,256] = A[M,K] @ W[K,256], fp16x2 split ----------------
// A exact to 2^-22 (fp16 hi/lo), B single fp16 plane. 2 HMMA per tile position.
// CTA 128x128, 8 warps (4 M x 2 N), warp tile 32x64, K chunk 32.
#define AROW 80
__global__ void __launch_bounds__(256, 2) gemm_mma(
    const float* __restrict__ A, const unsigned char* __restrict__ img,
    float* __restrict__ C, __half* __restrict__ C16, int K,
    const float* __restrict__ bias, const float* __restrict__ gamma,
    const float* __restrict__ beta, const float* __restrict__ mu,
    const float* __restrict__ var, int mode)
{
    __shared__ float s_sc[128];
    __shared__ float s_sh[128];
    __shared__ __align__(16) unsigned char s_ah[128 * AROW];
    __shared__ __align__(16) unsigned char s_al[128 * AROW];
    __shared__ __align__(16) unsigned char s_b[128 * AROW];

    int tid = threadIdx.x;
    int wid = tid >> 5, lane = tid & 31;
    int wm = wid & 3, wn = wid >> 2;          // 4 M-warps x 2 N-warps
    int m0 = blockIdx.x * 128;
    int bn = blockIdx.y;                      // N half (0/1)

    if (tid < 128) {
        int col = bn * 128 + tid;
        float s, h;
        if (mode == 0) {
            s = gamma[col] * rsqrtf(var[col] + BN_EPS);
            h = beta[col] + (bias[col] - mu[col]) * s;
        } else {
            s = 1.f;
            h = bias[col];
        }
        s_sc[tid] = s;
        s_sh[tid] = h;
    }

    float acc[2][8][4];
#pragma unroll
    for (int i = 0; i < 2; i++)
#pragma unroll
        for (int j = 0; j < 8; j++)
#pragma unroll
            for (int q = 0; q < 4; q++) acc[i][j][q] = 0.f;

    uint32_t ah_b = smem_u32(s_ah), al_b = smem_u32(s_al);
    uint32_t b_bb = smem_u32(s_b);
    int l16 = lane & 15;
    uint32_t a_off = (uint32_t)((wm * 32 + l16) * AROW + (lane >> 4) * 16);
    uint32_t b_off = (uint32_t)((wn * 64 + (l16 & 7)) * AROW + ((l16 >> 3) & 1) * 16);

    int nchunk = K >> 5;
    for (int c = 0; c < nchunk; c++) {
        if (c) __syncthreads();
        // ---- A chunk: 128 rows x 32 k fp32 -> fp16 hi/lo ----
#pragma unroll
        for (int i = 0; i < 4; i++) {
            int idx = tid + i * 256;
            int row = idx >> 3, q = idx & 7;
            float4 v = make_float4(0.f, 0.f, 0.f, 0.f);
            if (m0 + row < NODES)
                v = *(const float4*)&A[(size_t)(m0 + row) * K + c * 32 + q * 4];
            unsigned short h0, h1, h2, h3, l0, l1, l2, l3;
            hsplit(v.x, h0, l0); hsplit(v.y, h1, l1);
            hsplit(v.z, h2, l2); hsplit(v.w, h3, l3);
            uint2 hp = make_uint2(((uint32_t)h1 << 16) | h0, ((uint32_t)h3 << 16) | h2);
            uint2 lp = make_uint2(((uint32_t)l1 << 16) | l0, ((uint32_t)l3 << 16) | l2);
            *(uint2*)(s_ah + row * AROW + q * 8) = hp;
            *(uint2*)(s_al + row * AROW + q * 8) = lp;
        }
        // ---- B chunk: 128 n-rows x 32 k fp16 (pre-rounded, k-major): 512 uint4 ----
#pragma unroll
        for (int i = 0; i < 2; i++) {
            int idx = tid + i * 256;
            int row = idx >> 2, q = idx & 3;
            size_t srcoff = ((size_t)(bn * 128 + row) * K + c * 32) * 2 + q * 16;
            *(uint4*)(s_b + row * AROW + q * 16) = *(const uint4*)(img + srcoff);
        }
        __syncthreads();

#pragma unroll
        for (int ks = 0; ks < 2; ks++) {
            uint32_t a_hi[2][4], a_lo[2][4];
#pragma unroll
            for (int mt = 0; mt < 2; mt++) {
                ldsm4(a_hi[mt], ah_b + a_off + mt * 16 * AROW + ks * 32);
                ldsm4(a_lo[mt], al_b + a_off + mt * 16 * AROW + ks * 32);
            }
#pragma unroll
            for (int nh = 0; nh < 2; nh++) {
                uint32_t b_r[4][2];
#pragma unroll
                for (int t4 = 0; t4 < 4; t4++) {
                    int nt = nh * 4 + t4;
                    ldsm2(b_r[t4], b_bb + b_off + nt * 8 * AROW + ks * 32);
                }
#pragma unroll
                for (int mt = 0; mt < 2; mt++)
#pragma unroll
                    for (int t4 = 0; t4 < 4; t4++) {
                        int nt = nh * 4 + t4;
                        mma16816h(acc[mt][nt], a_hi[mt], b_r[t4]);
                        mma16816h(acc[mt][nt], a_lo[mt], b_r[t4]);
                    }
            }
        }
    }

    // ---- epilogue ----
#pragma unroll
    for (int mt = 0; mt < 2; mt++) {
        int row0 = m0 + wm * 32 + mt * 16 + (lane >> 2);
#pragma unroll
        for (int nt = 0; nt < 8; nt++) {
            int colL = wn * 64 + nt * 8 + (lane & 3) * 2;
            float sc0 = s_sc[colL], sc1 = s_sc[colL + 1];
            float sh0 = s_sh[colL], sh1 = s_sh[colL + 1];
            float v0 = acc[mt][nt][0] * sc0 + sh0;
            float v1 = acc[mt][nt][1] * sc1 + sh1;
            float v2 = acc[mt][nt][2] * sc0 + sh0;
            float v3 = acc[mt][nt][3] * sc1 + sh1;
            if (mode < 2) {
                v0 = fmaxf(v0, 0.f); v1 = fmaxf(v1, 0.f);
                v2 = fmaxf(v2, 0.f); v3 = fmaxf(v3, 0.f);
            }
            int colG = bn * 128 + colL;
            if (row0 < NODES) {
                *(float2*)&C[(size_t)row0 * 256 + colG] = make_float2(v0, v1);
                if (mode == 1)
                    *(__half2*)&C16[(size_t)row0 * 256 + colG] = __floats2half2_rn(v0, v1);
            }
            if (row0 + 8 < NODES) {
                *(float2*)&C[(size_t)(row0 + 8) * 256 + colG] = make_float2(v2, v3);
                if (mode == 1)
                    *(__half2*)&C16[(size_t)(row0 + 8) * 256 + colG] = __floats2half2_rn(v2, v3);
            }
        }
    }
}

// ---------------- output head ----------------
__global__ void out_kernel(const float* __restrict__ h, const float* __restrict__ W,
                           const float* __restrict__ b, float* __restrict__ out) {
    int gw = (blockIdx.x * blockDim.x + threadIdx.x) >> 5;
    int lane = threadIdx.x & 31;
    if (gw >= NODES) return;
    const float* row = h + (size_t)gw * 256;
    float a0 = 0.f, a1 = 0.f;
    for (int k = lane; k < 256; k += 32) {
        float v = row[k];
        a0 += v * W[k * 2];
        a1 += v * W[k * 2 + 1];
    }
#pragma unroll
    for (int o = 16; o > 0; o >>= 1) {
        a0 += __shfl_down_sync(0xFFFFFFFFu, a0, o);
        a1 += __shfl_down_sync(0xFFFFFFFFu, a1, o);
    }
    if (lane == 0) {
        out[gw * 2]     = a0 + b[0];
        out[gw * 2 + 1] = a1 + b[1];
    }
}

// ---------------- launch ----------------
extern "C" void kernel_launch(void* const* d_in, const int* in_sizes, int n_in,
                              void* d_out, int out_size) {
    const float* x   = (const float*)d_in[0];
    const int*   ei  = (const int*)d_in[1];
    const int*   src = ei;
    const int*   dst = ei + EDGES;

    const float* L[3][8];
    for (int l = 0; l < 3; l++)
        for (int p = 0; p < 8; p++)
            L[l][p] = (const float*)d_in[2 + l * 8 + p];
    const float* out_W = (const float*)d_in[26];
    const float* out_b = (const float*)d_in[27];
    float* out = (float*)d_out;

    float* zp; cudaGetSymbolAddress((void**)&zp, g_z);
    float* mp; cudaGetSymbolAddress((void**)&mp, g_m);
    float* hp; cudaGetSymbolAddress((void**)&hp, g_h);
    __half* h16; cudaGetSymbolAddress((void**)&h16, g_h16);
    unsigned char* wimg; cudaGetSymbolAddress((void**)&wimg, g_wimg);

    // CSR build
    zero_counts_kernel<<<(NODES + 255) / 256, 256>>>();
    hist_kernel<<<(EDGES + 255) / 256, 256>>>(dst);
    scan1_kernel<<<SCAN_NB, SCAN_CHUNK>>>();
    scan2_kernel<<<1, 128>>>();
    scan3_kernel<<<SCAN_NB, SCAN_CHUNK>>>();
    scatter_kernel<<<(EDGES + 255) / 256, 256>>>(src, dst);

    // weight images + x fp16 mirror
    const float* Ws[6] = { L[0][0], L[0][6], L[1][0], L[1][6], L[2][0], L[2][6] };
    int Ks[6] = { 128, 256, 256, 256, 256, 256 };
    for (int i = 0; i < 6; i++) {
        int total = 256 * Ks[i];
        prep_kernel<<<(total + 255) / 256, 256>>>(Ws[i], Ks[i], wimg + (size_t)i * 131072);
    }
    xhalf_kernel<<<(NODES * 32 + 255) / 256, 256>>>(x, h16);

    dim3 ggrid((NODES + 127) / 128, 2);   // 782 x 2

    // layer 1  (gather x in fp16; h16 holds x16 with stride 128)
    agg_kernel<128><<<(NODES + 15) / 16, dim3(16, 16)>>>(x, h16, zp);
    gemm_mma<<<ggrid, 256>>>(zp, wimg + 0 * 131072, mp, nullptr, 128,
                             L[0][1], L[0][2], L[0][3], L[0][4], L[0][5], 0);
    gemm_mma<<<ggrid, 256>>>(mp, wimg + 1 * 131072, hp, h16, 256,
                             L[0][7], nullptr, nullptr, nullptr, nullptr, 1);
    // layer 2
    agg_kernel<256><<<(NODES + 7) / 8, dim3(32, 8)>>>(hp, h16, zp);
    gemm_mma<<<ggrid, 256>>>(zp, wimg + 2 * 131072, mp, nullptr, 256,
                             L[1][1], L[1][2], L[1][3], L[1][4], L[1][5], 0);
    gemm_mma<<<ggrid, 256>>>(mp, wimg + 3 * 131072, hp, h16, 256,
                             L[1][7], nullptr, nullptr, nullptr, nullptr, 1);
    // layer 3
    agg_kernel<256><<<(NODES + 7) / 8, dim3(32, 8)>>>(hp, h16, zp);
    gemm_mma<<<ggrid, 256>>>(zp, wimg + 4 * 131072, mp, nullptr, 256,
                             L[2][1], L[2][2], L[2][3], L[2][4], L[2][5], 0);
    gemm_mma<<<ggrid, 256>>>(mp, wimg + 5 * 131072, hp, nullptr, 256,
                             L[2][7], nullptr, nullptr, nullptr, nullptr, 2);

    // output head
    out_kernel<<<(NODES * 32 + 255) / 256, 256>>>(hp, out_W, out_b, out);
}

// round 12
// speedup vs baseline: 1.9976x; 1.1334x over previous
#include <cuda_runtime.h>
#include <cuda_bf16.h>
#include <cuda_fp16.h>
#include <cstdint>

#define NODES 100000
#define EDGES 3200000
#define BN_EPS 1e-5f

// ---------------- scratch (no allocation allowed) ----------------
__device__ float g_z[NODES * 256];   // z = h + agg
__device__ float g_m[NODES * 256];   // after first linear+BN+ReLU
__device__ float g_h[NODES * 256];   // layer output (fp32)
__device__ __align__(16) __half g_h16[NODES * 256];  // fp16 mirror for gather
__device__ int   g_counts[NODES];
__device__ int   g_offsets[NODES];
__device__ int   g_cursor[NODES];
__device__ int   g_blocksums[128];
__device__ int   g_csr[EDGES];
// weight images per GEMM: Bt[256][K] fp16 (k-major), one plane
__device__ __align__(16) unsigned char g_wimg[6][131072];

// ---------------- helpers ----------------
__device__ __forceinline__ uint32_t smem_u32(const void* p) {
    uint32_t a;
    asm("{ .reg .u64 t; cvta.to.shared.u64 t, %1; cvt.u32.u64 %0, t; }" : "=r"(a) : "l"(p));
    return a;
}
__device__ __forceinline__ void ldsm4(uint32_t* r, uint32_t addr) {
    asm volatile("ldmatrix.sync.aligned.m8n8.x4.shared.b16 {%0,%1,%2,%3}, [%4];"
        : "=r"(r[0]), "=r"(r[1]), "=r"(r[2]), "=r"(r[3]) : "r"(addr));
}
__device__ __forceinline__ void ldsm2(uint32_t* r, uint32_t addr) {
    asm volatile("ldmatrix.sync.aligned.m8n8.x2.shared.b16 {%0,%1}, [%2];"
        : "=r"(r[0]), "=r"(r[1]) : "r"(addr));
}
__device__ __forceinline__ void mma16816h(float* d, const uint32_t* a, const uint32_t* b) {
    asm volatile(
        "mma.sync.aligned.m16n8k16.row.col.f32.f16.f16.f32 "
        "{%0,%1,%2,%3}, {%4,%5,%6,%7}, {%8,%9}, {%0,%1,%2,%3};"
        : "+f"(d[0]), "+f"(d[1]), "+f"(d[2]), "+f"(d[3])
        : "r"(a[0]), "r"(a[1]), "r"(a[2]), "r"(a[3]), "r"(b[0]), "r"(b[1]));
}

// ---------------- CSR build ----------------
__global__ void zero_counts_kernel() {
    int i = blockIdx.x * blockDim.x + threadIdx.x;
    if (i < NODES) g_counts[i] = 0;
}
__global__ void hist_kernel(const int* __restrict__ dst) {
    int e = blockIdx.x * blockDim.x + threadIdx.x;
    if (e < EDGES) atomicAdd(&g_counts[dst[e]], 1);
}
#define SCAN_CHUNK 1024
#define SCAN_NB ((NODES + SCAN_CHUNK - 1) / SCAN_CHUNK)   // 98
__global__ void scan1_kernel() {
    __shared__ int s[SCAN_CHUNK];
    int t = threadIdx.x;
    int i = blockIdx.x * SCAN_CHUNK + t;
    s[t] = (i < NODES) ? g_counts[i] : 0;
    __syncthreads();
    for (int d = SCAN_CHUNK / 2; d > 0; d >>= 1) {
        if (t < d) s[t] += s[t + d];
        __syncthreads();
    }
    if (t == 0) g_blocksums[blockIdx.x] = s[0];
}
__global__ void scan2_kernel() {
    __shared__ int s[128];
    int t = threadIdx.x;
    int v = (t < SCAN_NB) ? g_blocksums[t] : 0;
    s[t] = v;
    __syncthreads();
    for (int d = 1; d < 128; d <<= 1) {
        int x = (t >= d) ? s[t - d] : 0;
        __syncthreads();
        s[t] += x;
        __syncthreads();
    }
    g_blocksums[t] = s[t] - v;   // exclusive
}
__global__ void scan3_kernel() {
    __shared__ int s[SCAN_CHUNK];
    int t = threadIdx.x;
    int i = blockIdx.x * SCAN_CHUNK + t;
    int v = (i < NODES) ? g_counts[i] : 0;
    s[t] = v;
    __syncthreads();
    for (int d = 1; d < SCAN_CHUNK; d <<= 1) {
        int x = (t >= d) ? s[t - d] : 0;
        __syncthreads();
        s[t] += x;
        __syncthreads();
    }
    int off = g_blocksums[blockIdx.x] + s[t] - v;
    if (i < NODES) {
        g_offsets[i] = off;
        g_cursor[i]  = off;
    }
}
__global__ void scatter_kernel(const int* __restrict__ src, const int* __restrict__ dst) {
    int e = blockIdx.x * blockDim.x + threadIdx.x;
    if (e < EDGES) {
        int d = dst[e];
        int pos = atomicAdd(&g_cursor[d], 1);
        g_csr[pos] = src[e];
    }
}

// ---------------- x -> fp16 convert (for layer-1 gather) ----------------
__global__ void xhalf_kernel(const float* __restrict__ x, __half* __restrict__ x16) {
    int t = blockIdx.x * blockDim.x + threadIdx.x;   // one per 4 floats
    if (t < NODES * 32) {
        float4 v = ((const float4*)x)[t];
        __half2 a = __floats2half2_rn(v.x, v.y);
        __half2 b = __floats2half2_rn(v.z, v.w);
        ((__half2*)x16)[t * 2]     = a;
        ((__half2*)x16)[t * 2 + 1] = b;
    }
}

// ---------------- aggregation: self fp32 + fp16 neighbor gather (depth-1 prefetch) ----------------
template <int F>
__global__ void agg_kernel(const float* __restrict__ hf, const __half* __restrict__ h16,
                           float* __restrict__ z) {
    constexpr int TPN = F / 8;                // lanes per node (8 features each)
    constexpr int NPB = 256 / TPN;
    int node = blockIdx.x * NPB + threadIdx.y;
    if (node >= NODES) return;
    int f = threadIdx.x;
    const float4* selfp = (const float4*)(hf + (size_t)node * F) + f * 2;
    float4 a0 = selfp[0], a1 = selfp[1];
    float acc0 = a0.x, acc1 = a0.y, acc2 = a0.z, acc3 = a0.w;
    float acc4 = a1.x, acc5 = a1.y, acc6 = a1.z, acc7 = a1.w;
    const uint4* __restrict__ g16 = (const uint4*)h16;
    int beg = g_offsets[node];
    int cnt = g_counts[node];
#define ACCQ(Q) do { \
        float2 p0 = __half22float2(*(__half2*)&(Q).x); \
        float2 p1 = __half22float2(*(__half2*)&(Q).y); \
        float2 p2 = __half22float2(*(__half2*)&(Q).z); \
        float2 p3 = __half22float2(*(__half2*)&(Q).w); \
        acc0 += p0.x; acc1 += p0.y; acc2 += p1.x; acc3 += p1.y; \
        acc4 += p2.x; acc5 += p2.y; acc6 += p3.x; acc7 += p3.y; } while (0)
    if (cnt > 0) {
        int j = g_csr[beg];
        uint4 q = __ldg(&g16[(size_t)j * TPN + f]);
        for (int k = 1; k < cnt; k++) {
            int jn = g_csr[beg + k];
            uint4 qn = __ldg(&g16[(size_t)jn * TPN + f]);
            ACCQ(q);
            q = qn;
        }
        ACCQ(q);
    }
#undef ACCQ
    float4* zp = (float4*)(z + (size_t)node * F) + f * 2;
    zp[0] = make_float4(acc0, acc1, acc2, acc3);
    zp[1] = make_float4(acc4, acc5, acc6, acc7);
}

// ---------------- weight prep: W[K,256] fp32 -> Bt[256][K] fp16 (k-major) ----------------
__global__ void prep_kernel(const float* __restrict__ W, int K, unsigned char* __restrict__ img) {
    int t = blockIdx.x * blockDim.x + threadIdx.x;
    if (t >= 256 * K) return;
    int n = t / K;
    int k = t % K;
    float v = W[(size_t)k * 256 + n];
    __half hb = __float2half_rn(v);
    ((unsigned short*)img)[t] = reinterpret_cast<unsigned short&>(hb);
}

// ---------------- tensor-core GEMM: C[M,256] = A[M,K] @ W[K,256], fp16 single ----------------
// A and B rounded to fp16, fp32 accumulate. 1 HMMA per tile position.
// CTA 128x128, 8 warps (4 M x 2 N), warp tile 32x64, K chunk 32.
#define AROW 80
__global__ void __launch_bounds__(256, 2) gemm_mma(
    const float* __restrict__ A, const unsigned char* __restrict__ img,
    float* __restrict__ C, __half* __restrict__ C16, int K,
    const float* __restrict__ bias, const float* __restrict__ gamma,
    const float* __restrict__ beta, const float* __restrict__ mu,
    const float* __restrict__ var, int mode)
{
    __shared__ float s_sc[128];
    __shared__ float s_sh[128];
    __shared__ __align__(16) unsigned char s_a[128 * AROW];
    __shared__ __align__(16) unsigned char s_b[128 * AROW];

    int tid = threadIdx.x;
    int wid = tid >> 5, lane = tid & 31;
    int wm = wid & 3, wn = wid >> 2;          // 4 M-warps x 2 N-warps
    int m0 = blockIdx.x * 128;
    int bn = blockIdx.y;                      // N half (0/1)

    if (tid < 128) {
        int col = bn * 128 + tid;
        float s, h;
        if (mode == 0) {
            s = gamma[col] * rsqrtf(var[col] + BN_EPS);
            h = beta[col] + (bias[col] - mu[col]) * s;
        } else {
            s = 1.f;
            h = bias[col];
        }
        s_sc[tid] = s;
        s_sh[tid] = h;
    }

    float acc[2][8][4];
#pragma unroll
    for (int i = 0; i < 2; i++)
#pragma unroll
        for (int j = 0; j < 8; j++)
#pragma unroll
            for (int q = 0; q < 4; q++) acc[i][j][q] = 0.f;

    uint32_t a_bb = smem_u32(s_a);
    uint32_t b_bb = smem_u32(s_b);
    int l16 = lane & 15;
    uint32_t a_off = (uint32_t)((wm * 32 + l16) * AROW + (lane >> 4) * 16);
    uint32_t b_off = (uint32_t)((wn * 64 + (l16 & 7)) * AROW + ((l16 >> 3) & 1) * 16);

    int nchunk = K >> 5;
    for (int c = 0; c < nchunk; c++) {
        if (c) __syncthreads();
        // ---- A chunk: 128 rows x 32 k fp32 -> fp16 ----
#pragma unroll
        for (int i = 0; i < 4; i++) {
            int idx = tid + i * 256;
            int row = idx >> 3, q = idx & 7;
            float4 v = make_float4(0.f, 0.f, 0.f, 0.f);
            if (m0 + row < NODES)
                v = *(const float4*)&A[(size_t)(m0 + row) * K + c * 32 + q * 4];
            __half2 p0 = __floats2half2_rn(v.x, v.y);
            __half2 p1 = __floats2half2_rn(v.z, v.w);
            uint2 hp;
            hp.x = reinterpret_cast<uint32_t&>(p0);
            hp.y = reinterpret_cast<uint32_t&>(p1);
            *(uint2*)(s_a + row * AROW + q * 8) = hp;
        }
        // ---- B chunk: 128 n-rows x 32 k fp16 (pre-rounded, k-major): 512 uint4 ----
#pragma unroll
        for (int i = 0; i < 2; i++) {
            int idx = tid + i * 256;
            int row = idx >> 2, q = idx & 3;
            size_t srcoff = ((size_t)(bn * 128 + row) * K + c * 32) * 2 + q * 16;
            *(uint4*)(s_b + row * AROW + q * 16) = *(const uint4*)(img + srcoff);
        }
        __syncthreads();

#pragma unroll
        for (int ks = 0; ks < 2; ks++) {
            uint32_t a_r[2][4];
#pragma unroll
            for (int mt = 0; mt < 2; mt++)
                ldsm4(a_r[mt], a_bb + a_off + mt * 16 * AROW + ks * 32);
#pragma unroll
            for (int nh = 0; nh < 2; nh++) {
                uint32_t b_r[4][2];
#pragma unroll
                for (int t4 = 0; t4 < 4; t4++) {
                    int nt = nh * 4 + t4;
                    ldsm2(b_r[t4], b_bb + b_off + nt * 8 * AROW + ks * 32);
                }
#pragma unroll
                for (int mt = 0; mt < 2; mt++)
#pragma unroll
                    for (int t4 = 0; t4 < 4; t4++) {
                        int nt = nh * 4 + t4;
                        mma16816h(acc[mt][nt], a_r[mt], b_r[t4]);
                    }
            }
        }
    }

    // ---- epilogue ----
#pragma unroll
    for (int mt = 0; mt < 2; mt++) {
        int row0 = m0 + wm * 32 + mt * 16 + (lane >> 2);
#pragma unroll
        for (int nt = 0; nt < 8; nt++) {
            int colL = wn * 64 + nt * 8 + (lane & 3) * 2;
            float sc0 = s_sc[colL], sc1 = s_sc[colL + 1];
            float sh0 = s_sh[colL], sh1 = s_sh[colL + 1];
            float v0 = acc[mt][nt][0] * sc0 + sh0;
            float v1 = acc[mt][nt][1] * sc1 + sh1;
            float v2 = acc[mt][nt][2] * sc0 + sh0;
            float v3 = acc[mt][nt][3] * sc1 + sh1;
            if (mode < 2) {
                v0 = fmaxf(v0, 0.f); v1 = fmaxf(v1, 0.f);
                v2 = fmaxf(v2, 0.f); v3 = fmaxf(v3, 0.f);
            }
            int colG = bn * 128 + colL;
            if (row0 < NODES) {
                *(float2*)&C[(size_t)row0 * 256 + colG] = make_float2(v0, v1);
                if (mode == 1)
                    *(__half2*)&C16[(size_t)row0 * 256 + colG] = __floats2half2_rn(v0, v1);
            }
            if (row0 + 8 < NODES) {
                *(float2*)&C[(size_t)(row0 + 8) * 256 + colG] = make_float2(v2, v3);
                if (mode == 1)
                    *(__half2*)&C16[(size_t)(row0 + 8) * 256 + colG] = __floats2half2_rn(v2, v3);
            }
        }
    }
}

// ---------------- output head ----------------
__global__ void out_kernel(const float* __restrict__ h, const float* __restrict__ W,
                           const float* __restrict__ b, float* __restrict__ out) {
    int gw = (blockIdx.x * blockDim.x + threadIdx.x) >> 5;
    int lane = threadIdx.x & 31;
    if (gw >= NODES) return;
    const float* row = h + (size_t)gw * 256;
    float a0 = 0.f, a1 = 0.f;
    for (int k = lane; k < 256; k += 32) {
        float v = row[k];
        a0 += v * W[k * 2];
        a1 += v * W[k * 2 + 1];
    }
#pragma unroll
    for (int o = 16; o > 0; o >>= 1) {
        a0 += __shfl_down_sync(0xFFFFFFFFu, a0, o);
        a1 += __shfl_down_sync(0xFFFFFFFFu, a1, o);
    }
    if (lane == 0) {
        out[gw * 2]     = a0 + b[0];
        out[gw * 2 + 1] = a1 + b[1];
    }
}

// ---------------- launch ----------------
extern "C" void kernel_launch(void* const* d_in, const int* in_sizes, int n_in,
                              void* d_out, int out_size) {
    const float* x   = (const float*)d_in[0];
    const int*   ei  = (const int*)d_in[1];
    const int*   src = ei;
    const int*   dst = ei + EDGES;

    const float* L[3][8];
    for (int l = 0; l < 3; l++)
        for (int p = 0; p < 8; p++)
            L[l][p] = (const float*)d_in[2 + l * 8 + p];
    const float* out_W = (const float*)d_in[26];
    const float* out_b = (const float*)d_in[27];
    float* out = (float*)d_out;

    float* zp; cudaGetSymbolAddress((void**)&zp, g_z);
    float* mp; cudaGetSymbolAddress((void**)&mp, g_m);
    float* hp; cudaGetSymbolAddress((void**)&hp, g_h);
    __half* h16; cudaGetSymbolAddress((void**)&h16, g_h16);
    unsigned char* wimg; cudaGetSymbolAddress((void**)&wimg, g_wimg);

    // CSR build
    zero_counts_kernel<<<(NODES + 255) / 256, 256>>>();
    hist_kernel<<<(EDGES + 255) / 256, 256>>>(dst);
    scan1_kernel<<<SCAN_NB, SCAN_CHUNK>>>();
    scan2_kernel<<<1, 128>>>();
    scan3_kernel<<<SCAN_NB, SCAN_CHUNK>>>();
    scatter_kernel<<<(EDGES + 255) / 256, 256>>>(src, dst);

    // weight images + x fp16 mirror
    const float* Ws[6] = { L[0][0], L[0][6], L[1][0], L[1][6], L[2][0], L[2][6] };
    int Ks[6] = { 128, 256, 256, 256, 256, 256 };
    for (int i = 0; i < 6; i++) {
        int total = 256 * Ks[i];
        prep_kernel<<<(total + 255) / 256, 256>>>(Ws[i], Ks[i], wimg + (size_t)i * 131072);
    }
    xhalf_kernel<<<(NODES * 32 + 255) / 256, 256>>>(x, h16);

    dim3 ggrid((NODES + 127) / 128, 2);   // 782 x 2

    // layer 1  (gather x in fp16; h16 holds x16 with stride 128)
    agg_kernel<128><<<(NODES + 15) / 16, dim3(16, 16)>>>(x, h16, zp);
    gemm_mma<<<ggrid, 256>>>(zp, wimg + 0 * 131072, mp, nullptr, 128,
                             L[0][1], L[0][2], L[0][3], L[0][4], L[0][5], 0);
    gemm_mma<<<ggrid, 256>>>(mp, wimg + 1 * 131072, hp, h16, 256,
                             L[0][7], nullptr, nullptr, nullptr, nullptr, 1);
    // layer 2
    agg_kernel<256><<<(NODES + 7) / 8, dim3(32, 8)>>>(hp, h16, zp);
    gemm_mma<<<ggrid, 256>>>(zp, wimg + 2 * 131072, mp, nullptr, 256,
                             L[1][1], L[1][2], L[1][3], L[1][4], L[1][5], 0);
    gemm_mma<<<ggrid, 256>>>(mp, wimg + 3 * 131072, hp, h16, 256,
                             L[1][7], nullptr, nullptr, nullptr, nullptr, 1);
    // layer 3
    agg_kernel<256><<<(NODES + 7) / 8, dim3(32, 8)>>>(hp, h16, zp);
    gemm_mma<<<ggrid, 256>>>(zp, wimg + 4 * 131072, mp, nullptr, 256,
                             L[2][1], L[2][2], L[2][3], L[2][4], L[2][5], 0);
    gemm_mma<<<ggrid, 256>>>(mp, wimg + 5 * 131072, hp, nullptr, 256,
                             L[2][7], nullptr, nullptr, nullptr, nullptr, 2);

    // output head
    out_kernel<<<(NODES * 32 + 255) / 256, 256>>>(hp, out_W, out_b, out);
}